// round 3
// baseline (speedup 1.0000x reference)
#include <cuda_runtime.h>
#include <cuda_bf16.h>

static constexpr int BATCH = 2048;
static constexpr int NSLOT = 64;
static constexpr int FEAT  = 19;
static constexpr int WPC   = 4;              // warps (=batches) per CTA
static constexpr int GRID  = BATCH / WPC;    // 512 CTAs

__device__ float g_blockpart[GRID];
__device__ int   g_count = 0;                // self-resetting -> graph-replay safe

__global__ __launch_bounds__(32 * WPC) void spotting_kernel(
    const float* __restrict__ y_true,
    const float* __restrict__ y_pred,
    float*       __restrict__ out)
{
    const int w = threadIdx.x >> 5;      // warp (= batch slot) in CTA
    const int l = threadIdx.x & 31;      // lane
    const int b = blockIdx.x * WPC + w;  // batch

    __shared__ float              s_yt[WPC][NSLOT * FEAT];
    __shared__ float              s_yp[WPC][NSLOT * FEAT];
    __shared__ float              s_p[WPC][NSLOT];       // p_j; taken -> 1e30
    __shared__ unsigned long long s_ck[WPC][NSLOT];      // column proposal key
    __shared__ int                s_r2c[WPC][NSLOT];     // row -> column
    __shared__ float              s_wpart[WPC];
    __shared__ int                s_flag;

    // ---- coalesced stage of this batch ----
    {
        const float* yt = y_true + (size_t)b * NSLOT * FEAT;
        const float* yp = y_pred + (size_t)b * NSLOT * FEAT;
        #pragma unroll
        for (int k = l; k < NSLOT * FEAT; k += 32) {
            s_yt[w][k] = yt[k];
            s_yp[w][k] = yp[k];
        }
    }
    __syncwarp();

    const int r0 = l, r1 = l + 32;       // two rows / two columns per lane
    #pragma unroll
    for (int r = l; r < NSLOT; r += 32) {
        s_p[w][r]   = s_yp[w][r * FEAT + 1];
        s_ck[w][r]  = 0ULL;
        s_r2c[w][r] = -1;
    }
    __syncwarp();

    const float a0 = s_yt[w][r0 * FEAT + 0], x0 = s_yt[w][r0 * FEAT + 1];
    const float a1 = s_yt[w][r1 * FEAT + 0], x1 = s_yt[w][r1 * FEAT + 1];

    // ---- greedy mutual-best matching, proposal-cached ----
    // Phase 0: alpha==1 rows; Phase 1: alpha==0 rows (taken columns persist).
    #pragma unroll 1
    for (int phase = 0; phase < 2; ++phase) {
        const bool inp0 = (phase == 0) ? (a0 > 0.5f) : (a0 <= 0.5f);
        const bool inp1 = (phase == 0) ? (a1 > 0.5f) : (a1 <= 0.5f);

        int   bj0 = -1, bj1 = -1;        // cached proposal (column)
        float bv0 = 0.f, bv1 = 0.f;      // cached proposal (value)

        for (;;) {
            const bool act0 = inp0 && (s_r2c[w][r0] < 0);
            const bool act1 = inp1 && (s_r2c[w][r1] < 0);
            if (__all_sync(0xffffffffu, !act0 && !act1)) break;

            // Rescan only if no cached proposal or its column was taken.
            // Caching is exact: removals can never beat the current best.
            if (act0 && (bj0 < 0 || s_p[w][bj0] > 1e29f)) {
                bv0 = -3e38f; bj0 = 0;
                #pragma unroll 8
                for (int j = 0; j < NSLOT; ++j) {
                    const float d = 1.0f - fabsf(x0 - s_p[w][j]);
                    if (d > bv0) { bv0 = d; bj0 = j; }   // strict > = argmax tie-break
                }
            }
            if (act1 && (bj1 < 0 || s_p[w][bj1] > 1e29f)) {
                bv1 = -3e38f; bj1 = 0;
                #pragma unroll 8
                for (int j = 0; j < NSLOT; ++j) {
                    const float d = 1.0f - fabsf(x1 - s_p[w][j]);
                    if (d > bv1) { bv1 = d; bj1 = j; }
                }
            }
            // Propose: key = (value desc, row asc); bv>0 so key != 0.
            if (act0) atomicMax(&s_ck[w][bj0],
                ((unsigned long long)__float_as_uint(bv0) << 6) |
                (unsigned long long)(63 - r0));
            if (act1) atomicMax(&s_ck[w][bj1],
                ((unsigned long long)__float_as_uint(bv1) << 6) |
                (unsigned long long)(63 - r1));
            __syncwarp();

            // Column accept: every proposed column takes its best proposer
            // (exactly E = v*A*C: mutual best = best proposer).
            #pragma unroll
            for (int c = l; c < NSLOT; c += 32) {
                const unsigned long long k = s_ck[w][c];
                if (k) {
                    const int r = 63 - (int)(k & 63ULL);
                    s_r2c[w][r] = c;
                    s_p[w][c]   = 1e30f;   // remove column
                    s_ck[w][c]  = 0ULL;
                }
            }
            __syncwarp();
        }
    }

    // ---- loss: lane handles its two rows against permuted prediction ----
    float loss = 0.0f;
    #pragma unroll
    for (int t = 0; t < 2; ++t) {
        const int   r  = (t == 0) ? r0 : r1;
        const float a  = (t == 0) ? a0 : a1;
        const float x  = (t == 0) ? x0 : x1;
        const int   pi = s_r2c[w][r];
        const float* ypp = &s_yp[w][pi * FEAT];
        const float* ytr = &s_yt[w][r  * FEAT];

        const float d1 = x - ypp[1];
        const float d0 = a - ypp[0];
        float lv = a * 5.0f * d1 * d1
                 + a * d0 * d0
                 + (1.0f - a) * 0.5f * d0 * d0;
        float s2 = 0.0f;
        #pragma unroll
        for (int f = 2; f < FEAT; ++f) {
            const float d = ytr[f] - ypp[f];
            s2 += d * d;
        }
        loss = loss + lv + a * s2;
    }

    // Deterministic warp butterfly reduce
    #pragma unroll
    for (int off = 16; off > 0; off >>= 1)
        loss += __shfl_xor_sync(0xffffffffu, loss, off);
    if (l == 0) s_wpart[w] = loss;
    __syncthreads();

    // Single writer per block publishes its partial, then last block reduces.
    if (threadIdx.x == 0) {
        float v = s_wpart[0] + s_wpart[1] + s_wpart[2] + s_wpart[3];
        g_blockpart[blockIdx.x] = v;
        __threadfence();
        const int t = atomicAdd(&g_count, 1);
        s_flag = (t == GRID - 1);
    }
    __syncthreads();

    if (s_flag) {
        __shared__ float sred[32 * WPC];
        float v = 0.0f;
        #pragma unroll
        for (int k = 0; k < GRID / (32 * WPC); ++k)
            v += g_blockpart[threadIdx.x + k * 32 * WPC];   // fixed order
        sred[threadIdx.x] = v;
        __syncthreads();
        #pragma unroll
        for (int off = (32 * WPC) / 2; off > 0; off >>= 1) {
            if (threadIdx.x < off) sred[threadIdx.x] += sred[threadIdx.x + off];
            __syncthreads();
        }
        if (threadIdx.x == 0) {
            out[0]  = sred[0];
            g_count = 0;                 // reset for next graph replay
        }
    }
}

extern "C" void kernel_launch(void* const* d_in, const int* in_sizes, int n_in,
                              void* d_out, int out_size)
{
    const float* y_true = (const float*)d_in[0];
    const float* y_pred = (const float*)d_in[1];
    float*       out    = (float*)d_out;

    spotting_kernel<<<GRID, 32 * WPC>>>(y_true, y_pred, out);
}